// round 2
// baseline (speedup 1.0000x reference)
#include <cuda_runtime.h>
#include <cuda_bf16.h>
#include <math.h>

// Problem dims
#define BB 2048
#define SS 32
#define DD 1024
#define PP 16
#define FF 512
#define HH 512

// ---------------- scratch layout (single __device__ array, no allocs) -------
// sizes in floats
#define N_T1    ((size_t)BB * SS * DD)        // 67,108,864
#define N_VP    ((size_t)BB * SS * DD)
#define N_H     ((size_t)BB * SS * HH)        // 33,554,432
#define N_ATTN  ((size_t)BB * SS * SS)        // 2,097,152
#define N_GU    ((size_t)BB * SS)
#define N_GV    ((size_t)BB * SS)
#define N_DAV   ((size_t)BB * SS)
#define N_AVPRE ((size_t)2 * BB * DD)
#define N_FAV   ((size_t)3 * BB * DD)
#define N_HEAD  ((size_t)3 * BB * FF)
#define N_MT    ((size_t)DD * DD)

#define OF_T1    ((size_t)0)
#define OF_VP    (OF_T1 + N_T1)
#define OF_H     (OF_VP + N_VP)
#define OF_ATTN  (OF_H + N_H)
#define OF_GU    (OF_ATTN + N_ATTN)
#define OF_GV    (OF_GU + N_GU)
#define OF_DAV   (OF_GV + N_GV)
#define OF_AVPRE (OF_DAV + N_DAV)
#define OF_FAV   (OF_AVPRE + N_AVPRE)
#define OF_HEAD  (OF_FAV + N_FAV)
#define OF_MT    (OF_HEAD + N_HEAD)
#define OF_WU    (OF_MT + N_MT)
#define OF_WV    (OF_WU + 1024)
#define OF_C     (OF_WV + 1024)
#define SCRATCH_FLOATS (OF_C + 16)

__device__ float g_scratch[SCRATCH_FLOATS];

// ---------------------------------------------------------------------------
// Generic NT SGEMM: C[m,n] = sum_k A[m,k] * Bt[n,k] (+ bias[n]) (+ relu)
// Block tile 128x128, BK=8, 256 threads, 8x8 microtile.
// Grid: (N/128, M/128, Z). z-strides applied to A, Bt, bias, C.
// ---------------------------------------------------------------------------
__global__ __launch_bounds__(256, 2)
void sgemm_nt(const float* __restrict__ A, int lda, long long zA,
              const float* __restrict__ Bt, int ldb, long long zB,
              const float* __restrict__ bias, long long zBias,
              float* __restrict__ C, int ldc, long long zC,
              int K, int relu)
{
    A  += (long long)blockIdx.z * zA;
    Bt += (long long)blockIdx.z * zB;
    C  += (long long)blockIdx.z * zC;
    if (bias) bias += (long long)blockIdx.z * zBias;

    __shared__ float As[8][128];
    __shared__ float Bs[8][128];

    const int tid = threadIdx.x;
    const int bm = blockIdx.y * 128;
    const int bn = blockIdx.x * 128;

    const int lrow = tid >> 1;          // 0..127
    const int lc4  = (tid & 1) * 4;     // 0 or 4

    const float* aptr = A  + (long long)(bm + lrow) * lda + lc4;
    const float* bptr = Bt + (long long)(bn + lrow) * ldb + lc4;

    const int tx = (tid & 15) * 8;      // n offset in tile
    const int ty = (tid >> 4) * 8;      // m offset in tile

    float acc[8][8];
#pragma unroll
    for (int i = 0; i < 8; i++)
#pragma unroll
        for (int j = 0; j < 8; j++) acc[i][j] = 0.0f;

    for (int k0 = 0; k0 < K; k0 += 8) {
        float4 av = *(const float4*)(aptr + k0);
        float4 bv = *(const float4*)(bptr + k0);
        As[lc4 + 0][lrow] = av.x; As[lc4 + 1][lrow] = av.y;
        As[lc4 + 2][lrow] = av.z; As[lc4 + 3][lrow] = av.w;
        Bs[lc4 + 0][lrow] = bv.x; Bs[lc4 + 1][lrow] = bv.y;
        Bs[lc4 + 2][lrow] = bv.z; Bs[lc4 + 3][lrow] = bv.w;
        __syncthreads();
#pragma unroll
        for (int kk = 0; kk < 8; kk++) {
            float ra[8], rb[8];
            *(float4*)&ra[0] = *(const float4*)&As[kk][ty];
            *(float4*)&ra[4] = *(const float4*)&As[kk][ty + 4];
            *(float4*)&rb[0] = *(const float4*)&Bs[kk][tx];
            *(float4*)&rb[4] = *(const float4*)&Bs[kk][tx + 4];
#pragma unroll
            for (int i = 0; i < 8; i++)
#pragma unroll
                for (int j = 0; j < 8; j++)
                    acc[i][j] += ra[i] * rb[j];
        }
        __syncthreads();
    }

    float bb[8];
#pragma unroll
    for (int j = 0; j < 8; j++) bb[j] = bias ? bias[bn + tx + j] : 0.0f;

#pragma unroll
    for (int i = 0; i < 8; i++) {
        long long crow = (long long)(bm + ty + i) * ldc + bn + tx;
#pragma unroll
        for (int j4 = 0; j4 < 2; j4++) {
            float4 o;
            o.x = acc[i][j4 * 4 + 0] + bb[j4 * 4 + 0];
            o.y = acc[i][j4 * 4 + 1] + bb[j4 * 4 + 1];
            o.z = acc[i][j4 * 4 + 2] + bb[j4 * 4 + 2];
            o.w = acc[i][j4 * 4 + 3] + bb[j4 * 4 + 3];
            if (relu) {
                o.x = fmaxf(o.x, 0.0f); o.y = fmaxf(o.y, 0.0f);
                o.z = fmaxf(o.z, 0.0f); o.w = fmaxf(o.w, 0.0f);
            }
            *(float4*)(C + crow + j4 * 4) = o;
        }
    }
}

// ---------------------------------------------------------------------------
// TN SGEMM for Mt[n,k] = sum_e Wk[e,n] * Wq[e,k]  (all dims 1024)
// C is written so that C[n*1024+k] = M[k,n] where M = Wq^T Wk.
// ---------------------------------------------------------------------------
__global__ __launch_bounds__(256, 2)
void sgemm_tn_1024(const float* __restrict__ A,   // Wk [E,1024]
                   const float* __restrict__ Bm,  // Wq [E,1024]
                   float* __restrict__ C)         // [1024,1024]
{
    __shared__ float As[8][128];
    __shared__ float Bs[8][128];
    const int tid = threadIdx.x;
    const int bm = blockIdx.y * 128;  // n dim
    const int bn = blockIdx.x * 128;  // k dim
    const int le = tid >> 5;          // 0..7
    const int lc4 = (tid & 31) * 4;   // 0..124

    const int tx = (tid & 15) * 8;
    const int ty = (tid >> 4) * 8;

    float acc[8][8];
#pragma unroll
    for (int i = 0; i < 8; i++)
#pragma unroll
        for (int j = 0; j < 8; j++) acc[i][j] = 0.0f;

    for (int e0 = 0; e0 < 1024; e0 += 8) {
        *(float4*)&As[le][lc4] = *(const float4*)(A  + (long long)(e0 + le) * 1024 + bm + lc4);
        *(float4*)&Bs[le][lc4] = *(const float4*)(Bm + (long long)(e0 + le) * 1024 + bn + lc4);
        __syncthreads();
#pragma unroll
        for (int kk = 0; kk < 8; kk++) {
            float ra[8], rb[8];
            *(float4*)&ra[0] = *(const float4*)&As[kk][ty];
            *(float4*)&ra[4] = *(const float4*)&As[kk][ty + 4];
            *(float4*)&rb[0] = *(const float4*)&Bs[kk][tx];
            *(float4*)&rb[4] = *(const float4*)&Bs[kk][tx + 4];
#pragma unroll
            for (int i = 0; i < 8; i++)
#pragma unroll
                for (int j = 0; j < 8; j++)
                    acc[i][j] += ra[i] * rb[j];
        }
        __syncthreads();
    }
#pragma unroll
    for (int i = 0; i < 8; i++) {
        long long crow = (long long)(bm + ty + i) * 1024 + bn + tx;
#pragma unroll
        for (int j4 = 0; j4 < 2; j4++) {
            float4 o;
            o.x = acc[i][j4 * 4 + 0]; o.y = acc[i][j4 * 4 + 1];
            o.z = acc[i][j4 * 4 + 2]; o.w = acc[i][j4 * 4 + 3];
            *(float4*)(C + crow + j4 * 4) = o;
        }
    }
}

// ---------------------------------------------------------------------------
// Bias-fold vectors: w_u[k]=sum_e Wq[e,k]*bk[e]; w_v[k]=sum_e Wk[e,k]*bq[e];
// c = bq.bk  (all zero for the actual dataset, kept for generality)
// ---------------------------------------------------------------------------
__global__ void vec_kernel(const float* __restrict__ in_w,
                           const float* __restrict__ in_b,
                           float* __restrict__ wu, float* __restrict__ wv,
                           float* __restrict__ cp)
{
    int k = blockIdx.x * 256 + threadIdx.x;  // 0..1023
    const float* wq = in_w;
    const float* wk = in_w + (size_t)DD * DD;
    const float* bq = in_b;
    const float* bk = in_b + DD;
    float su = 0.0f, sv = 0.0f;
    for (int e = 0; e < DD; e++) {
        su += wq[(size_t)e * DD + k] * bk[e];
        sv += wk[(size_t)e * DD + k] * bq[e];
    }
    wu[k] = su; wv[k] = sv;
    if (k == 0) {
        float c = 0.0f;
        for (int e = 0; e < DD; e++) c += bq[e] * bk[e];
        cp[0] = c;
    }
}

// ---------------------------------------------------------------------------
// u[b,s] = q[b,s].w_u ;  v[b,s] = q[b,s].w_v
// ---------------------------------------------------------------------------
__global__ __launch_bounds__(1024)
void uv_kernel(const float* __restrict__ q,
               const float* __restrict__ wu, const float* __restrict__ wv,
               float* __restrict__ gu, float* __restrict__ gv)
{
    int b = blockIdx.x;
    int w = threadIdx.x >> 5, lane = threadIdx.x & 31;  // 32 warps
    const float* row = q + ((size_t)b * SS + w) * DD;
    float su = 0.0f, sv = 0.0f;
    for (int k = lane; k < DD; k += 32) {
        float qv = row[k];
        su += qv * wu[k];
        sv += qv * wv[k];
    }
#pragma unroll
    for (int o = 16; o; o >>= 1) {
        su += __shfl_down_sync(0xffffffffu, su, o);
        sv += __shfl_down_sync(0xffffffffu, sv, o);
    }
    if (lane == 0) { gu[b * SS + w] = su; gv[b * SS + w] = sv; }
}

// ---------------------------------------------------------------------------
// Per-batch attention: scores[s,t] = (t1[b,s].q[b,t] + u[s]+v[t]+c)/32,
// softmax over t -> attn[b,s,t]
// ---------------------------------------------------------------------------
__global__ __launch_bounds__(256)
void attn_kernel(const float* __restrict__ q, const float* __restrict__ t1,
                 const float* __restrict__ gu, const float* __restrict__ gv,
                 const float* __restrict__ cp, float* __restrict__ attn)
{
    int b = blockIdx.x;
    __shared__ float sq[32 * 65];
    __shared__ float st[32 * 65];
    __shared__ float ssc[32 * 33];
    const float* qb = q  + (size_t)b * SS * DD;
    const float* tb = t1 + (size_t)b * SS * DD;
    int tid = threadIdx.x;
    int t = tid & 31, s0 = tid >> 5;
    float acc0 = 0, acc1 = 0, acc2 = 0, acc3 = 0;

    for (int kc = 0; kc < DD; kc += 64) {
        for (int i = tid; i < 32 * 16; i += 256) {
            int r = i >> 4, c4 = (i & 15) * 4;
            float4 a = *(const float4*)(qb + (size_t)r * DD + kc + c4);
            float4 v = *(const float4*)(tb + (size_t)r * DD + kc + c4);
            sq[r * 65 + c4 + 0] = a.x; sq[r * 65 + c4 + 1] = a.y;
            sq[r * 65 + c4 + 2] = a.z; sq[r * 65 + c4 + 3] = a.w;
            st[r * 65 + c4 + 0] = v.x; st[r * 65 + c4 + 1] = v.y;
            st[r * 65 + c4 + 2] = v.z; st[r * 65 + c4 + 3] = v.w;
        }
        __syncthreads();
#pragma unroll 8
        for (int kk = 0; kk < 64; kk++) {
            float rq = sq[t * 65 + kk];
            acc0 += st[(s0 +  0) * 65 + kk] * rq;
            acc1 += st[(s0 +  8) * 65 + kk] * rq;
            acc2 += st[(s0 + 16) * 65 + kk] * rq;
            acc3 += st[(s0 + 24) * 65 + kk] * rq;
        }
        __syncthreads();
    }
    float c = cp[0];
    float vv = gv[b * SS + t];
    const float sc = 1.0f / 32.0f;
    ssc[(s0 +  0) * 33 + t] = (acc0 + gu[b * SS + s0 +  0] + vv + c) * sc;
    ssc[(s0 +  8) * 33 + t] = (acc1 + gu[b * SS + s0 +  8] + vv + c) * sc;
    ssc[(s0 + 16) * 33 + t] = (acc2 + gu[b * SS + s0 + 16] + vv + c) * sc;
    ssc[(s0 + 24) * 33 + t] = (acc3 + gu[b * SS + s0 + 24] + vv + c) * sc;
    __syncthreads();
    if (tid < 32) {
        float mx = -1e30f;
        for (int j = 0; j < 32; j++) mx = fmaxf(mx, ssc[tid * 33 + j]);
        float sum = 0.0f;
        for (int j = 0; j < 32; j++) {
            float e = expf(ssc[tid * 33 + j] - mx);
            ssc[tid * 33 + j] = e; sum += e;
        }
        float inv = 1.0f / sum;
        for (int j = 0; j < 32; j++)
            attn[(size_t)b * SS * SS + tid * 32 + j] = ssc[tid * 33 + j] * inv;
    }
}

// ---------------------------------------------------------------------------
// Classifier head: d[b,s] = relu(h[b,s,:].w2[s,:] + b2[s]); softmax halves
// -> writes d_a, d_v to d_out tail AND to scratch dav.
// ---------------------------------------------------------------------------
__global__ __launch_bounds__(512)
void cls_head_kernel(const float* __restrict__ h, const float* __restrict__ w2,
                     const float* __restrict__ b2, float* __restrict__ dav,
                     float* __restrict__ out_d)
{
    int b = blockIdx.x;
    __shared__ float sd[32];
    int w = threadIdx.x >> 5, lane = threadIdx.x & 31;  // 16 warps
    for (int s = w; s < SS; s += 16) {
        const float* hr = h + ((size_t)b * SS + s) * HH;
        const float* wr = w2 + (size_t)s * HH;
        float acc = 0.0f;
        for (int k = lane; k < HH; k += 32) acc += hr[k] * wr[k];
#pragma unroll
        for (int o = 16; o; o >>= 1) acc += __shfl_down_sync(0xffffffffu, acc, o);
        if (lane == 0) sd[s] = fmaxf(acc + b2[s], 0.0f);
    }
    __syncthreads();
    if (threadIdx.x < 2) {
        int off = threadIdx.x * PP;  // 0 -> d_a, 1 -> d_v
        float mx = -1e30f;
        for (int j = 0; j < PP; j++) mx = fmaxf(mx, sd[off + j]);
        float sum = 0.0f;
        float e[PP];
        for (int j = 0; j < PP; j++) { e[j] = expf(sd[off + j] - mx); sum += e[j]; }
        float inv = 1.0f / sum;
        float* outp = out_d + (size_t)threadIdx.x * BB * PP + (size_t)b * PP;
        for (int j = 0; j < PP; j++) {
            float val = e[j] * inv;
            dav[b * SS + off + j] = val;
            outp[j] = val;
        }
    }
}

// ---------------------------------------------------------------------------
// combine: w_a[t] = sum_{s<16} d_a[s]*attn[s,t]; audio_pre = sum_t w_a[t]*vp[t,:]
// (same for video). Writes avpre rows [b] (audio) and [B+b] (video).
// ---------------------------------------------------------------------------
__global__ __launch_bounds__(128)
void combine_kernel(const float* __restrict__ attn, const float* __restrict__ vp,
                    const float* __restrict__ dav, float* __restrict__ avpre)
{
    int b = blockIdx.x;
    __shared__ float sat[SS * SS];
    __shared__ float wa[SS], wv_[SS];
    int tid = threadIdx.x;
    for (int i = tid; i < SS * SS; i += 128) sat[i] = attn[(size_t)b * SS * SS + i];
    __syncthreads();
    if (tid < SS) {
        float a = 0.0f, v = 0.0f;
        for (int s = 0; s < PP; s++) {
            a += dav[b * SS + s]      * sat[s * SS + tid];
            v += dav[b * SS + PP + s] * sat[(PP + s) * SS + tid];
        }
        wa[tid] = a; wv_[tid] = v;
    }
    __syncthreads();
    const float* vpb = vp + (size_t)b * SS * DD;
    for (int d = tid; d < DD; d += 128) {
        float a = 0.0f, v = 0.0f;
#pragma unroll
        for (int t = 0; t < SS; t++) {
            float x = vpb[(size_t)t * DD + d];
            a += wa[t] * x;
            v += wv_[t] * x;
        }
        avpre[(size_t)b * DD + d] = a;
        avpre[((size_t)BB + b) * DD + d] = v;
    }
}

// fusion = 0.5*(audio+video): fav[0..B) = 0.5*(fav[B..2B) + fav[2B..3B))
__global__ void avg_kernel(float* __restrict__ fav)
{
    size_t i = (size_t)blockIdx.x * 256 + threadIdx.x;
    fav[i] = 0.5f * (fav[(size_t)BB * DD + i] + fav[(size_t)2 * BB * DD + i]);
}

// ---------------------------------------------------------------------------
// LayerNorm(512) + ReLU over rows. 128 threads per row.
// ---------------------------------------------------------------------------
__global__ __launch_bounds__(128)
void ln_kernel(const float* __restrict__ x, const float* __restrict__ g,
               const float* __restrict__ be, float* __restrict__ out)
{
    int row = blockIdx.x;
    const float* xr = x + (size_t)row * FF;
    int tid = threadIdx.x;
    __shared__ float sm[4];
    float v[4];
    float s = 0.0f;
#pragma unroll
    for (int i = 0; i < 4; i++) { v[i] = xr[tid + 128 * i]; s += v[i]; }
#pragma unroll
    for (int o = 16; o; o >>= 1) s += __shfl_down_sync(0xffffffffu, s, o);
    if ((tid & 31) == 0) sm[tid >> 5] = s;
    __syncthreads();
    float mu = (sm[0] + sm[1] + sm[2] + sm[3]) * (1.0f / FF);
    __syncthreads();
    float q = 0.0f;
#pragma unroll
    for (int i = 0; i < 4; i++) { float d = v[i] - mu; q += d * d; }
#pragma unroll
    for (int o = 16; o; o >>= 1) q += __shfl_down_sync(0xffffffffu, q, o);
    if ((tid & 31) == 0) sm[tid >> 5] = q;
    __syncthreads();
    float var = (sm[0] + sm[1] + sm[2] + sm[3]) * (1.0f / FF);
    float rstd = rsqrtf(var + 1e-5f);
    float* orow = out + (size_t)row * FF;
#pragma unroll
    for (int i = 0; i < 4; i++) {
        int c = tid + 128 * i;
        float y = (v[i] - mu) * rstd * g[c] + be[c];
        orow[c] = fmaxf(y, 0.0f);
    }
}

// ---------------------------------------------------------------------------
extern "C" void kernel_launch(void* const* d_in, const int* in_sizes, int n_in,
                              void* d_out, int out_size)
{
    const float* q        = (const float*)d_in[0];
    const float* in_w     = (const float*)d_in[1];
    const float* in_b     = (const float*)d_in[2];
    const float* out_w    = (const float*)d_in[3];
    const float* out_b    = (const float*)d_in[4];
    const float* cls_w1   = (const float*)d_in[5];
    const float* cls_b1   = (const float*)d_in[6];
    const float* cls_w2   = (const float*)d_in[7];
    const float* cls_b2   = (const float*)d_in[8];
    const float* fus_w    = (const float*)d_in[9];
    const float* fus_b    = (const float*)d_in[10];
    const float* fus_g    = (const float*)d_in[11];
    const float* fus_be   = (const float*)d_in[12];
    const float* pa_w     = (const float*)d_in[13];
    const float* pa_b     = (const float*)d_in[14];
    const float* pa_g     = (const float*)d_in[15];
    const float* pa_be    = (const float*)d_in[16];
    const float* pv_w     = (const float*)d_in[17];
    const float* pv_b     = (const float*)d_in[18];
    const float* pv_g     = (const float*)d_in[19];
    const float* pv_be    = (const float*)d_in[20];
    float* out = (float*)d_out;

    float* sp = nullptr;
    cudaGetSymbolAddress((void**)&sp, g_scratch);

    float* t1    = sp + OF_T1;
    float* vp    = sp + OF_VP;
    float* h     = sp + OF_H;
    float* attn  = sp + OF_ATTN;
    float* gu    = sp + OF_GU;
    float* gv    = sp + OF_GV;
    float* dav   = sp + OF_DAV;
    float* avpre = sp + OF_AVPRE;
    float* fav   = sp + OF_FAV;
    float* headb = sp + OF_HEAD;
    float* Mt    = sp + OF_MT;
    float* wu    = sp + OF_WU;
    float* wv    = sp + OF_WV;
    float* cp    = sp + OF_C;

    const float* wk = in_w + (size_t)DD * DD;
    const float* wq = in_w;
    const float* wv_w = in_w + (size_t)2 * DD * DD;
    const float* bv = in_b + 2 * DD;

    // 1. Mt[n,k] = sum_e Wk[e,n]*Wq[e,k]   (so Mt is Bt-layout for t1 = q @ M)
    sgemm_tn_1024<<<dim3(8, 8, 1), 256>>>(wk, wq, Mt);
    // 2. bias-fold vectors
    vec_kernel<<<4, 256>>>(in_w, in_b, wu, wv, cp);
    // 3. t1 = q @ M     [65536,1024]
    sgemm_nt<<<dim3(8, 512, 1), 256>>>(q, DD, 0, Mt, DD, 0, nullptr, 0,
                                       t1, DD, 0, DD, 0);
    // 4. vp = q @ Wv^T + bv
    sgemm_nt<<<dim3(8, 512, 1), 256>>>(q, DD, 0, wv_w, DD, 0, bv, 0,
                                       vp, DD, 0, DD, 0);
    // 5. classifier hidden: h[b,s,:] = relu(q[b,s,:] @ W1[s]^T + b1[s])
    sgemm_nt<<<dim3(4, 16, 32), 256>>>(q, SS * DD, DD,
                                       cls_w1, DD, (long long)HH * DD,
                                       cls_b1, HH,
                                       h, SS * HH, HH,
                                       DD, 1);
    // 6. u, v vectors per (b,s)
    uv_kernel<<<BB, 1024>>>(q, wu, wv, gu, gv);
    // 7. attention softmax
    attn_kernel<<<BB, 256>>>(q, t1, gu, gv, cp, attn);
    // 8. classifier scalar + softmax halves -> d_a/d_v (out tail + scratch)
    cls_head_kernel<<<BB, 512>>>(h, cls_w2, cls_b2, dav,
                                 out + (size_t)3 * BB * FF);
    // 9. weighted position sums -> avpre (audio rows [0,B), video rows [B,2B))
    combine_kernel<<<BB, 128>>>(attn, vp, dav, avpre);
    // 10. out-projection of audio/video: fav[B..3B) = avpre @ out_w^T + out_b
    sgemm_nt<<<dim3(8, 32, 1), 256>>>(avpre, DD, 0, out_w, DD, 0, out_b, 0,
                                      fav + (size_t)BB * DD, DD, 0, DD, 0);
    // 11. fusion = 0.5*(audio+video) -> fav[0..B)
    avg_kernel<<<(BB * DD) / 256, 256>>>(fav);
    // 12-14. projector head GEMMs -> headb
    sgemm_nt<<<dim3(4, 16, 1), 256>>>(fav, DD, 0, fus_w, DD, 0, fus_b, 0,
                                      headb, FF, 0, DD, 0);
    sgemm_nt<<<dim3(4, 16, 1), 256>>>(fav + (size_t)BB * DD, DD, 0, pa_w, DD, 0,
                                      pa_b, 0, headb + (size_t)BB * FF, FF, 0, DD, 0);
    sgemm_nt<<<dim3(4, 16, 1), 256>>>(fav + (size_t)2 * BB * DD, DD, 0, pv_w, DD, 0,
                                      pv_b, 0, headb + (size_t)2 * BB * FF, FF, 0, DD, 0);
    // 15-17. LayerNorm + ReLU -> outputs
    ln_kernel<<<BB, 128>>>(headb, fus_g, fus_be, out);
    ln_kernel<<<BB, 128>>>(headb + (size_t)BB * FF, pa_g, pa_be, out + (size_t)BB * FF);
    ln_kernel<<<BB, 128>>>(headb + (size_t)2 * BB * FF, pv_g, pv_be, out + (size_t)2 * BB * FF);
}

// round 4
// speedup vs baseline: 3.6835x; 3.6835x over previous
#include <cuda_runtime.h>
#include <cuda_bf16.h>
#include <stdint.h>
#include <math.h>

// Problem dims
#define BB 2048
#define SS 32
#define DD 1024
#define PP 16
#define FF 512
#define HH 512

// ---------------- scratch layout (single __device__ array) ------------------
#define N_T1    ((size_t)BB * SS * DD)
#define N_H     ((size_t)BB * SS * HH)
#define N_ATTN  ((size_t)BB * SS * SS)
#define N_GV    ((size_t)BB * SS)
#define N_DAV   ((size_t)BB * SS)
#define N_AVMIX ((size_t)2 * BB * DD)
#define N_AVPRE ((size_t)2 * BB * DD)
#define N_FAV   ((size_t)3 * BB * DD)
#define N_HEAD  ((size_t)3 * BB * FF)
#define N_MT    ((size_t)DD * DD)
#define N_WT    ((size_t)2 * DD * DD)

#define OF_T1    ((size_t)0)
#define OF_H     (OF_T1 + N_T1)
#define OF_ATTN  (OF_H + N_H)
#define OF_GV    (OF_ATTN + N_ATTN)
#define OF_DAV   (OF_GV + N_GV)
#define OF_AVMIX (OF_DAV + N_DAV)
#define OF_AVPRE (OF_AVMIX + N_AVMIX)
#define OF_FAV   (OF_AVPRE + N_AVPRE)
#define OF_HEAD  (OF_FAV + N_FAV)
#define OF_MT    (OF_HEAD + N_HEAD)
#define OF_WT    (OF_MT + N_MT)
#define OF_WV    (OF_WT + N_WT)
#define SCRATCH_FLOATS (OF_WV + 1024)

__device__ float g_scratch[SCRATCH_FLOATS];

// ======================= helpers ===========================================
__device__ __forceinline__ uint32_t smem_u32(const void* p) {
    uint32_t a;
    asm("{ .reg .u64 t; cvta.to.shared.u64 t, %1; cvt.u32.u64 %0, t; }"
        : "=r"(a) : "l"(p));
    return a;
}

__device__ __forceinline__ uint32_t pk2(__nv_bfloat16 a, __nv_bfloat16 b) {
    __nv_bfloat162 t = __halves2bfloat162(a, b);
    return *reinterpret_cast<uint32_t*>(&t);
}

#define LDSM_X4(r0, r1, r2, r3, addr) \
    asm volatile("ldmatrix.sync.aligned.m8n8.x4.shared.b16 {%0,%1,%2,%3}, [%4];" \
                 : "=r"(r0), "=r"(r1), "=r"(r2), "=r"(r3) : "r"(addr))

#define MMA16816(d, a, b0, b1) \
    asm volatile("mma.sync.aligned.m16n8k16.row.col.f32.bf16.bf16.f32 " \
                 "{%0,%1,%2,%3}, {%4,%5,%6,%7}, {%8,%9}, {%0,%1,%2,%3};" \
                 : "+f"((d)[0]), "+f"((d)[1]), "+f"((d)[2]), "+f"((d)[3]) \
                 : "r"((a)[0]), "r"((a)[1]), "r"((a)[2]), "r"((a)[3]), \
                   "r"(b0), "r"(b1))

// ===========================================================================
// Split-bf16 3-pass NT GEMM on HMMA (mma.sync m16n8k16):
//   C[m,n] = sum_k A[m,k]*Bt[n,k] (+bias[n]) (+relu), fp32 in/out, err ~1e-5
// Tile 128x128, BK=32, 256 threads (8 warps, warp tile 64x32).
// Smem planes: row stride 80 B (5*16) -> conflict-free ldmatrix.
// ===========================================================================
#define AST 80
#define PL_AHI 0
#define PL_ALO 10240
#define PL_BHI 20480
#define PL_BLO 30720

__global__ __launch_bounds__(256)
void mma_gemm(const float* __restrict__ A, long long lda, long long zA,
              const float* __restrict__ Bt, long long ldb, long long zB,
              const float* __restrict__ bias, long long zBias,
              float* __restrict__ C, long long ldc, long long zC,
              int K, int relu)
{
    __shared__ __align__(16) char smem[40960];
    const uint32_t sb = smem_u32(smem);

    A  += (long long)blockIdx.z * zA;
    Bt += (long long)blockIdx.z * zB;
    C  += (long long)blockIdx.z * zC;
    if (bias) bias += (long long)blockIdx.z * zBias;

    const int tid = threadIdx.x;
    const int wid = tid >> 5, lid = tid & 31;
    const long long bm = (long long)blockIdx.y * 128;
    const long long bn = (long long)blockIdx.x * 128;
    const int wm = (wid & 1) * 64;     // warp m offset in tile
    const int wn = (wid >> 1) * 32;    // warp n offset in tile

    float acc[4][4][4];
#pragma unroll
    for (int mt = 0; mt < 4; mt++)
#pragma unroll
        for (int nt = 0; nt < 4; nt++)
#pragma unroll
            for (int r = 0; r < 4; r++) acc[mt][nt][r] = 0.0f;

    // ldmatrix lane-address components
    const int q = lid >> 3, qr = lid & 7;

    // prefetch first slab into registers
    float4 pa[4], pb[4];
#pragma unroll
    for (int i = 0; i < 4; i++) {
        int idx = i * 256 + tid;
        int r = idx >> 3, c4 = idx & 7;
        pa[i] = *(const float4*)(A  + (bm + r) * lda + c4 * 4);
        pb[i] = *(const float4*)(Bt + (bn + r) * ldb + c4 * 4);
    }

    for (int k0 = 0; k0 < K; k0 += 32) {
        // ---- store prefetched slab to smem with bf16 hi/lo split ----
#pragma unroll
        for (int i = 0; i < 4; i++) {
            int idx = i * 256 + tid;
            int r = idx >> 3, c4 = idx & 7;
            float4 v = pa[i];
            __nv_bfloat16 h0 = __float2bfloat16_rn(v.x);
            __nv_bfloat16 h1 = __float2bfloat16_rn(v.y);
            __nv_bfloat16 h2 = __float2bfloat16_rn(v.z);
            __nv_bfloat16 h3 = __float2bfloat16_rn(v.w);
            __nv_bfloat16 l0 = __float2bfloat16_rn(v.x - __bfloat162float(h0));
            __nv_bfloat16 l1 = __float2bfloat16_rn(v.y - __bfloat162float(h1));
            __nv_bfloat16 l2 = __float2bfloat16_rn(v.z - __bfloat162float(h2));
            __nv_bfloat16 l3 = __float2bfloat16_rn(v.w - __bfloat162float(h3));
            *(uint2*)(smem + PL_AHI + r * AST + c4 * 8) = make_uint2(pk2(h0, h1), pk2(h2, h3));
            *(uint2*)(smem + PL_ALO + r * AST + c4 * 8) = make_uint2(pk2(l0, l1), pk2(l2, l3));
            v = pb[i];
            h0 = __float2bfloat16_rn(v.x); h1 = __float2bfloat16_rn(v.y);
            h2 = __float2bfloat16_rn(v.z); h3 = __float2bfloat16_rn(v.w);
            l0 = __float2bfloat16_rn(v.x - __bfloat162float(h0));
            l1 = __float2bfloat16_rn(v.y - __bfloat162float(h1));
            l2 = __float2bfloat16_rn(v.z - __bfloat162float(h2));
            l3 = __float2bfloat16_rn(v.w - __bfloat162float(h3));
            *(uint2*)(smem + PL_BHI + r * AST + c4 * 8) = make_uint2(pk2(h0, h1), pk2(h2, h3));
            *(uint2*)(smem + PL_BLO + r * AST + c4 * 8) = make_uint2(pk2(l0, l1), pk2(l2, l3));
        }
        __syncthreads();

        // ---- prefetch next slab ----
        if (k0 + 32 < K) {
#pragma unroll
            for (int i = 0; i < 4; i++) {
                int idx = i * 256 + tid;
                int r = idx >> 3, c4 = idx & 7;
                pa[i] = *(const float4*)(A  + (bm + r) * lda + k0 + 32 + c4 * 4);
                pb[i] = *(const float4*)(Bt + (bn + r) * ldb + k0 + 32 + c4 * 4);
            }
        }

        // ---- compute: two k16 steps, 3 passes each ----
#pragma unroll
        for (int kk = 0; kk < 32; kk += 16) {
            uint32_t ah[4][4], al[4][4], bh[2][4], bl[2][4];
            // A fragments: rows = m, quadrants: (q&1)->m+8, (q>>1)->k+8
#pragma unroll
            for (int mt = 0; mt < 4; mt++) {
                uint32_t row = wm + mt * 16 + (q & 1) * 8 + qr;
                uint32_t off = row * AST + kk * 2 + (q >> 1) * 16;
                LDSM_X4(ah[mt][0], ah[mt][1], ah[mt][2], ah[mt][3], sb + PL_AHI + off);
                LDSM_X4(al[mt][0], al[mt][1], al[mt][2], al[mt][3], sb + PL_ALO + off);
            }
            // B fragments: rows = n, quadrants: (q&1)->k+8, (q>>1)->n+8
#pragma unroll
            for (int nt2 = 0; nt2 < 2; nt2++) {
                uint32_t row = wn + nt2 * 16 + (q >> 1) * 8 + qr;
                uint32_t off = row * AST + kk * 2 + (q & 1) * 16;
                LDSM_X4(bh[nt2][0], bh[nt2][1], bh[nt2][2], bh[nt2][3], sb + PL_BHI + off);
                LDSM_X4(bl[nt2][0], bl[nt2][1], bl[nt2][2], bl[nt2][3], sb + PL_BLO + off);
            }
#pragma unroll
            for (int mt = 0; mt < 4; mt++) {
#pragma unroll
                for (int nt = 0; nt < 4; nt++) {
                    int n2 = nt >> 1, o = (nt & 1) * 2;
                    MMA16816(acc[mt][nt], ah[mt], bh[n2][o], bh[n2][o + 1]);
                    MMA16816(acc[mt][nt], ah[mt], bl[n2][o], bl[n2][o + 1]);
                    MMA16816(acc[mt][nt], al[mt], bh[n2][o], bh[n2][o + 1]);
                }
            }
        }
        __syncthreads();
    }

    // ---- epilogue: scatter fp32 accumulators ----
    const int mrow = lid >> 2, ncol = (lid & 3) * 2;
#pragma unroll
    for (int mt = 0; mt < 4; mt++) {
        long long r0 = bm + wm + mt * 16 + mrow;
        long long r1 = r0 + 8;
#pragma unroll
        for (int nt = 0; nt < 4; nt++) {
            long long col = bn + wn + nt * 8 + ncol;
            float b0 = 0.0f, b1 = 0.0f;
            if (bias) { b0 = bias[col]; b1 = bias[col + 1]; }
            float o0 = acc[mt][nt][0] + b0, o1 = acc[mt][nt][1] + b1;
            float o2 = acc[mt][nt][2] + b0, o3 = acc[mt][nt][3] + b1;
            if (relu) {
                o0 = fmaxf(o0, 0.0f); o1 = fmaxf(o1, 0.0f);
                o2 = fmaxf(o2, 0.0f); o3 = fmaxf(o3, 0.0f);
            }
            *(float2*)(C + r0 * ldc + col) = make_float2(o0, o1);
            *(float2*)(C + r1 * ldc + col) = make_float2(o2, o3);
        }
    }
}

// ---------------------------------------------------------------------------
// transpose 1024x1024 fp32 (z selects matrix): out[i,j] = in[j,i]
// ---------------------------------------------------------------------------
__global__ __launch_bounds__(256)
void tr1024(const float* __restrict__ in, float* __restrict__ out)
{
    __shared__ float t[32][33];
    in  += (size_t)blockIdx.z * DD * DD;
    out += (size_t)blockIdx.z * DD * DD;
    int x = blockIdx.x * 32 + threadIdx.x;
    int y = blockIdx.y * 32 + threadIdx.y;
#pragma unroll
    for (int i = 0; i < 4; i++)
        t[threadIdx.y + 8 * i][threadIdx.x] = in[(size_t)(y + 8 * i) * DD + x];
    __syncthreads();
    int x2 = blockIdx.y * 32 + threadIdx.x;
    int y2 = blockIdx.x * 32 + threadIdx.y;
#pragma unroll
    for (int i = 0; i < 4; i++)
        out[(size_t)(y2 + 8 * i) * DD + x2] = t[threadIdx.x][threadIdx.y + 8 * i];
}

// wv[k] = sum_e bq[e] * Wk[e,k]
__global__ void vec_kernel(const float* __restrict__ in_w,
                           const float* __restrict__ in_b,
                           float* __restrict__ wv)
{
    int k = blockIdx.x * 256 + threadIdx.x;
    const float* wkm = in_w + (size_t)DD * DD;
    const float* bq = in_b;
    float sv = 0.0f;
    for (int e = 0; e < DD; e++) sv += bq[e] * wkm[(size_t)e * DD + k];
    wv[k] = sv;
}

// gv[b,s] = q[b,s,:] . wv
__global__ __launch_bounds__(1024)
void uv_kernel(const float* __restrict__ q, const float* __restrict__ wv,
               float* __restrict__ gv)
{
    int b = blockIdx.x;
    int w = threadIdx.x >> 5, lane = threadIdx.x & 31;
    const float* row = q + ((size_t)b * SS + w) * DD;
    float sv = 0.0f;
    for (int k = lane; k < DD; k += 32) sv += row[k] * wv[k];
#pragma unroll
    for (int o = 16; o; o >>= 1) sv += __shfl_down_sync(0xffffffffu, sv, o);
    if (lane == 0) gv[b * SS + w] = sv;
}

// ---------------------------------------------------------------------------
// attention: scores[s,t] = (t1[b,s].q[b,t] + gv[t]) / 32, softmax over t
// ---------------------------------------------------------------------------
__global__ __launch_bounds__(256)
void attn_kernel(const float* __restrict__ q, const float* __restrict__ t1,
                 const float* __restrict__ gv, float* __restrict__ attn)
{
    int b = blockIdx.x;
    __shared__ float sq[32 * 65];
    __shared__ float st[32 * 65];
    __shared__ float ssc[32 * 33];
    const float* qb = q  + (size_t)b * SS * DD;
    const float* tbp = t1 + (size_t)b * SS * DD;
    int tid = threadIdx.x;
    int t = tid & 31, s0 = tid >> 5;
    float acc0 = 0, acc1 = 0, acc2 = 0, acc3 = 0;

    for (int kc = 0; kc < DD; kc += 64) {
        for (int i = tid; i < 32 * 16; i += 256) {
            int r = i >> 4, c4 = (i & 15) * 4;
            float4 a = *(const float4*)(qb + (size_t)r * DD + kc + c4);
            float4 v = *(const float4*)(tbp + (size_t)r * DD + kc + c4);
            sq[r * 65 + c4 + 0] = a.x; sq[r * 65 + c4 + 1] = a.y;
            sq[r * 65 + c4 + 2] = a.z; sq[r * 65 + c4 + 3] = a.w;
            st[r * 65 + c4 + 0] = v.x; st[r * 65 + c4 + 1] = v.y;
            st[r * 65 + c4 + 2] = v.z; st[r * 65 + c4 + 3] = v.w;
        }
        __syncthreads();
#pragma unroll 8
        for (int kk = 0; kk < 64; kk++) {
            float rq = sq[t * 65 + kk];
            acc0 += st[(s0 +  0) * 65 + kk] * rq;
            acc1 += st[(s0 +  8) * 65 + kk] * rq;
            acc2 += st[(s0 + 16) * 65 + kk] * rq;
            acc3 += st[(s0 + 24) * 65 + kk] * rq;
        }
        __syncthreads();
    }
    float vv = gv[b * SS + t];
    const float sc = 1.0f / 32.0f;
    ssc[(s0 +  0) * 33 + t] = (acc0 + vv) * sc;
    ssc[(s0 +  8) * 33 + t] = (acc1 + vv) * sc;
    ssc[(s0 + 16) * 33 + t] = (acc2 + vv) * sc;
    ssc[(s0 + 24) * 33 + t] = (acc3 + vv) * sc;
    __syncthreads();
    if (tid < 32) {
        float mx = -1e30f;
        for (int j = 0; j < 32; j++) mx = fmaxf(mx, ssc[tid * 33 + j]);
        float sum = 0.0f;
        for (int j = 0; j < 32; j++) {
            float e = expf(ssc[tid * 33 + j] - mx);
            ssc[tid * 33 + j] = e; sum += e;
        }
        float inv = 1.0f / sum;
        for (int j = 0; j < 32; j++)
            attn[(size_t)b * SS * SS + tid * 32 + j] = ssc[tid * 33 + j] * inv;
    }
}

// ---------------------------------------------------------------------------
// classifier scalar + softmax halves -> d_a/d_v (out tail + scratch)
// ---------------------------------------------------------------------------
__global__ __launch_bounds__(512)
void cls_head_kernel(const float* __restrict__ h, const float* __restrict__ w2,
                     const float* __restrict__ b2, float* __restrict__ dav,
                     float* __restrict__ out_d)
{
    int b = blockIdx.x;
    __shared__ float sd[32];
    int w = threadIdx.x >> 5, lane = threadIdx.x & 31;
    for (int s = w; s < SS; s += 16) {
        const float* hr = h + ((size_t)b * SS + s) * HH;
        const float* wr = w2 + (size_t)s * HH;
        float acc = 0.0f;
        for (int k = lane; k < HH; k += 32) acc += hr[k] * wr[k];
#pragma unroll
        for (int o = 16; o; o >>= 1) acc += __shfl_down_sync(0xffffffffu, acc, o);
        if (lane == 0) sd[s] = fmaxf(acc + b2[s], 0.0f);
    }
    __syncthreads();
    if (threadIdx.x < 2) {
        int off = threadIdx.x * PP;
        float mx = -1e30f;
        for (int j = 0; j < PP; j++) mx = fmaxf(mx, sd[off + j]);
        float sum = 0.0f;
        float e[PP];
        for (int j = 0; j < PP; j++) { e[j] = expf(sd[off + j] - mx); sum += e[j]; }
        float inv = 1.0f / sum;
        float* outp = out_d + (size_t)threadIdx.x * BB * PP + (size_t)b * PP;
        for (int j = 0; j < PP; j++) {
            float val = e[j] * inv;
            dav[b * SS + off + j] = val;
            outp[j] = val;
        }
    }
}

// ---------------------------------------------------------------------------
// mix in q-space: wa[t]=sum_s d_a[s]attn[s,t]; avmix_a[b]=sum_t wa[t] q[b,t,:]
// ---------------------------------------------------------------------------
__global__ __launch_bounds__(128)
void combine_kernel(const float* __restrict__ attn, const float* __restrict__ q,
                    const float* __restrict__ dav, float* __restrict__ avmix)
{
    int b = blockIdx.x;
    __shared__ float sat[SS * SS];
    __shared__ float wa[SS], wvv[SS];
    int tid = threadIdx.x;
    for (int i = tid; i < SS * SS; i += 128) sat[i] = attn[(size_t)b * SS * SS + i];
    __syncthreads();
    if (tid < SS) {
        float a = 0.0f, v = 0.0f;
        for (int s = 0; s < PP; s++) {
            a += dav[b * SS + s]      * sat[s * SS + tid];
            v += dav[b * SS + PP + s] * sat[(PP + s) * SS + tid];
        }
        wa[tid] = a; wvv[tid] = v;
    }
    __syncthreads();
    const float* qb = q + (size_t)b * SS * DD;
    for (int d = tid; d < DD; d += 128) {
        float a = 0.0f, v = 0.0f;
#pragma unroll
        for (int t = 0; t < SS; t++) {
            float x = qb[(size_t)t * DD + d];
            a += wa[t] * x;
            v += wvv[t] * x;
        }
        avmix[(size_t)b * DD + d] = a;
        avmix[((size_t)BB + b) * DD + d] = v;
    }
}

// fusion = 0.5*(audio+video)
__global__ void avg_kernel(float* __restrict__ fav)
{
    size_t i = (size_t)blockIdx.x * 256 + threadIdx.x;
    fav[i] = 0.5f * (fav[(size_t)BB * DD + i] + fav[(size_t)2 * BB * DD + i]);
}

// ---------------------------------------------------------------------------
// LayerNorm(512) + ReLU per row
// ---------------------------------------------------------------------------
__global__ __launch_bounds__(128)
void ln_kernel(const float* __restrict__ x, const float* __restrict__ g,
               const float* __restrict__ be, float* __restrict__ out)
{
    int row = blockIdx.x;
    const float* xr = x + (size_t)row * FF;
    int tid = threadIdx.x;
    __shared__ float sm[4];
    float v[4];
    float s = 0.0f;
#pragma unroll
    for (int i = 0; i < 4; i++) { v[i] = xr[tid + 128 * i]; s += v[i]; }
#pragma unroll
    for (int o = 16; o; o >>= 1) s += __shfl_down_sync(0xffffffffu, s, o);
    if ((tid & 31) == 0) sm[tid >> 5] = s;
    __syncthreads();
    float mu = (sm[0] + sm[1] + sm[2] + sm[3]) * (1.0f / FF);
    __syncthreads();
    float qv = 0.0f;
#pragma unroll
    for (int i = 0; i < 4; i++) { float d = v[i] - mu; qv += d * d; }
#pragma unroll
    for (int o = 16; o; o >>= 1) qv += __shfl_down_sync(0xffffffffu, qv, o);
    if ((tid & 31) == 0) sm[tid >> 5] = qv;
    __syncthreads();
    float var = (sm[0] + sm[1] + sm[2] + sm[3]) * (1.0f / FF);
    float rstd = rsqrtf(var + 1e-5f);
    float* orow = out + (size_t)row * FF;
#pragma unroll
    for (int i = 0; i < 4; i++) {
        int c = tid + 128 * i;
        float y = (v[i] - mu) * rstd * g[c] + be[c];
        orow[c] = fmaxf(y, 0.0f);
    }
}

// ---------------------------------------------------------------------------
extern "C" void kernel_launch(void* const* d_in, const int* in_sizes, int n_in,
                              void* d_out, int out_size)
{
    const float* q      = (const float*)d_in[0];
    const float* in_w   = (const float*)d_in[1];
    const float* in_b   = (const float*)d_in[2];
    const float* out_w  = (const float*)d_in[3];
    const float* out_b  = (const float*)d_in[4];
    const float* cls_w1 = (const float*)d_in[5];
    const float* cls_b1 = (const float*)d_in[6];
    const float* cls_w2 = (const float*)d_in[7];
    const float* cls_b2 = (const float*)d_in[8];
    const float* fus_w  = (const float*)d_in[9];
    const float* fus_b  = (const float*)d_in[10];
    const float* fus_g  = (const float*)d_in[11];
    const float* fus_be = (const float*)d_in[12];
    const float* pa_w   = (const float*)d_in[13];
    const float* pa_b   = (const float*)d_in[14];
    const float* pa_g   = (const float*)d_in[15];
    const float* pa_be  = (const float*)d_in[16];
    const float* pv_w   = (const float*)d_in[17];
    const float* pv_b   = (const float*)d_in[18];
    const float* pv_g   = (const float*)d_in[19];
    const float* pv_be  = (const float*)d_in[20];
    float* out = (float*)d_out;

    float* sp = nullptr;
    cudaGetSymbolAddress((void**)&sp, g_scratch);

    float* t1    = sp + OF_T1;
    float* h     = sp + OF_H;
    float* attn  = sp + OF_ATTN;
    float* gv    = sp + OF_GV;
    float* dav   = sp + OF_DAV;
    float* avmix = sp + OF_AVMIX;
    float* avpre = sp + OF_AVPRE;
    float* fav   = sp + OF_FAV;
    float* headb = sp + OF_HEAD;
    float* Mt    = sp + OF_MT;
    float* WqT   = sp + OF_WT;
    float* WkT   = sp + OF_WT + (size_t)DD * DD;
    float* wv    = sp + OF_WV;

    const float* wv_w = in_w + (size_t)2 * DD * DD;
    const float* bv = in_b + 2 * DD;

    // 1. WqT, WkT transposes
    tr1024<<<dim3(32, 32, 2), dim3(32, 8)>>>(in_w, WqT);
    // 2. bias fold
    vec_kernel<<<4, 256>>>(in_w, in_b, wv);
    // 3. Mt[n,k] = sum_e WkT[n,e]*WqT[k,e]
    mma_gemm<<<dim3(8, 8, 1), 256>>>(WkT, DD, 0, WqT, DD, 0, nullptr, 0,
                                     Mt, DD, 0, DD, 0);
    // 4. t1 = q @ M
    mma_gemm<<<dim3(8, 512, 1), 256>>>(q, DD, 0, Mt, DD, 0, nullptr, 0,
                                       t1, DD, 0, DD, 0);
    // 5. classifier hidden h = relu(q @ W1[s]^T + b1[s])
    mma_gemm<<<dim3(4, 16, 32), 256>>>(q, SS * DD, DD,
                                       cls_w1, DD, (long long)HH * DD,
                                       cls_b1, HH, h, SS * HH, HH, DD, 1);
    // 6. gv
    uv_kernel<<<BB, 1024>>>(q, wv, gv);
    // 7. attention softmax
    attn_kernel<<<BB, 256>>>(q, t1, gv, attn);
    // 8. classifier head -> dav + out tail
    cls_head_kernel<<<BB, 512>>>(h, cls_w2, cls_b2, dav, out + (size_t)3 * BB * FF);
    // 9. q-space mix
    combine_kernel<<<BB, 128>>>(attn, q, dav, avmix);
    // 10. avpre = avmix @ Wv^T + bv
    mma_gemm<<<dim3(8, 32, 1), 256>>>(avmix, DD, 0, wv_w, DD, 0, bv, 0,
                                      avpre, DD, 0, DD, 0);
    // 11. audio/video = avpre @ out_w^T + out_b -> fav[B..3B)
    mma_gemm<<<dim3(8, 32, 1), 256>>>(avpre, DD, 0, out_w, DD, 0, out_b, 0,
                                      fav + (size_t)BB * DD, DD, 0, DD, 0);
    // 12. fusion
    avg_kernel<<<(BB * DD) / 256, 256>>>(fav);
    // 13-15. projector heads
    mma_gemm<<<dim3(4, 16, 1), 256>>>(fav, DD, 0, fus_w, DD, 0, fus_b, 0,
                                      headb, FF, 0, DD, 0);
    mma_gemm<<<dim3(4, 16, 1), 256>>>(fav + (size_t)BB * DD, DD, 0, pa_w, DD, 0,
                                      pa_b, 0, headb + (size_t)BB * FF, FF, 0, DD, 0);
    mma_gemm<<<dim3(4, 16, 1), 256>>>(fav + (size_t)2 * BB * DD, DD, 0, pv_w, DD, 0,
                                      pv_b, 0, headb + (size_t)2 * BB * FF, FF, 0, DD, 0);
    // 16-18. LayerNorm + ReLU
    ln_kernel<<<BB, 128>>>(headb, fus_g, fus_be, out);
    ln_kernel<<<BB, 128>>>(headb + (size_t)BB * FF, pa_g, pa_be, out + (size_t)BB * FF);
    ln_kernel<<<BB, 128>>>(headb + (size_t)2 * BB * FF, pv_g, pv_be, out + (size_t)2 * BB * FF);
}